// round 16
// baseline (speedup 1.0000x reference)
#include <cuda_runtime.h>
#include <cuda_fp16.h>
#include <cstdint>
#include <cstddef>

// Problem constants (fixed by the dataset)
#define N_ROWS_MAX 1000000
#define NLOCS      100000
#define NTIMES     169
#define NUSERS1    50001
#define MCONST     100000u                  // any M > max(x) preserves (t,x) lex order
#define HMAX       (NLOCS * NTIMES)         // 16,900,000
#define TILE_H     8192                     // hashes per emit tile
#define NTILES     ((HMAX + TILE_H - 1) / TILE_H)   // 2063
#define CMASK      0x03FFFFFFu
#define VALMASK    0x3FFFFFFFu
#define FLAG_AGG   (1u << 30)
#define FLAG_INC   (2u << 30)
#define MAXSLOTS   500000                   // multi-count groups <= N/2

// ---------------- device scratch ----------------
// INVARIANT: d_cnt is all-zero at kernel_launch entry. Zero-init at module
// load covers the first call; k_out restores zeros for every touched entry
// (the group hashes in d_g2) at the end of every call.
__device__ unsigned d_cnt[HMAX];                      // (count<<26)|sum_u  (multi: |slot)
__device__ unsigned d_tilestate[NTILES];              // decoupled-lookback states
__device__ uint2    d_g2[N_ROWS_MAX];                 // (hash, packed word) per group
__device__ float    d_usum2[(size_t)MAXSLOTS * 128];  // per-slot SUM of C[u] (projected)
__device__ __half   d_Ah[(size_t)NLOCS * 128];        // fp16 W_loc @ loc_emb
__device__ __half   d_Bh[NTIMES * 128];               // fp16 W_time @ time_emb + bias
__device__ __half   d_Ch[(size_t)NUSERS1 * 128];      // fp16 W_user @ user_emb
__device__ unsigned d_nuniq;
__device__ unsigned d_mslots;                         // multi-slot allocator

// ================= launch 0: fused count + precompute tables + resets ========
#define NCNT    ((N_ROWS_MAX + 255) / 256)      // 3907
#define B0      (NCNT)
#define C0      (B0 + NTIMES)
#define NCB     ((NUSERS1 + 127) / 128)         // 391
#define A0      (C0 + NCB)
#define NAB     (NLOCS / 32)                    // 3125
#define PREGRID (A0 + NAB)

__global__ __launch_bounds__(256) void k_prec(
    const float* __restrict__ W, const float* __restrict__ loc_emb,
    const float* __restrict__ time_emb, const float* __restrict__ user_emb,
    const float* __restrict__ bias,
    const int* __restrict__ x, const int* __restrict__ t, const int* __restrict__ u,
    int n)
{
    __shared__ unsigned char smpool[41216];
    const int tid = threadIdx.x;
    const int b = blockIdx.x;

    if (b < NCNT) {
        // block 0 additionally resets lookback states + scalars (read next launch)
        if (b == 0) {
            for (int j = tid; j < NTILES; j += 256) d_tilestate[j] = 0;
            if (tid == 0) { d_nuniq = 0; d_mslots = 0; }
        }
        // ---- histogram count + packed user id ----
        int i = b * 256 + tid;
        if (i < n) {
            unsigned h = (unsigned)t[i] * MCONST + (unsigned)x[i];
            atomicAdd(&d_cnt[h], (1u << 26) | (unsigned)u[i]);
        }
    } else if (b < C0) {
        // ---- B table (one t per block), fp16 with bias folded ----
        int tt = b - B0;
        if (tid < 128) {
            int d = tid;
            float acc = bias[d];
            #pragma unroll
            for (int k = 0; k < 32; k++) acc += W[d * 128 + 64 + k] * time_emb[tt * 32 + k];
            d_Bh[tt * 128 + d] = __float2half_rn(acc);
        }
    } else if (b < A0) {
        // ---- C table: smem-tiled GEMM, 128 users per block ----
        float* Wu = (float*)smpool;                   // [32][136]
        float* Ue = (float*)(smpool + 32 * 136 * 4);  // [32][136]
        int ub = (b - C0) * 128;
        for (int i = tid; i < 128 * 32; i += 256) {
            int d = i >> 5, k = i & 31;
            Wu[k * 136 + d] = W[d * 128 + 96 + k];
        }
        for (int i = tid; i < 128 * 32; i += 256) {
            int r = i >> 5, k = i & 31;
            int uu = ub + r;
            Ue[k * 136 + r] = (uu < NUSERS1) ? user_emb[(size_t)uu * 32 + k] : 0.f;
        }
        __syncthreads();
        int tu = tid >> 4, td = tid & 15;
        float acc[8][8] = {};
        #pragma unroll
        for (int k = 0; k < 32; k++) {
            float4 u0 = *(const float4*)&Ue[k * 136 + tu * 8];
            float4 u1 = *(const float4*)&Ue[k * 136 + tu * 8 + 4];
            float4 w0 = *(const float4*)&Wu[k * 136 + td * 8];
            float4 w1 = *(const float4*)&Wu[k * 136 + td * 8 + 4];
            float uv[8] = {u0.x, u0.y, u0.z, u0.w, u1.x, u1.y, u1.z, u1.w};
            float wv[8] = {w0.x, w0.y, w0.z, w0.w, w1.x, w1.y, w1.z, w1.w};
            #pragma unroll
            for (int j = 0; j < 8; j++)
                #pragma unroll
                for (int m = 0; m < 8; m++) acc[j][m] += uv[j] * wv[m];
        }
        #pragma unroll
        for (int j = 0; j < 8; j++) {
            int uu = ub + tu * 8 + j;
            if (uu < NUSERS1) {
                __half hh[8];
                #pragma unroll
                for (int m = 0; m < 8; m++) hh[m] = __float2half_rn(acc[j][m]);
                *(uint4*)&d_Ch[(size_t)uu * 128 + td * 8] = *(const uint4*)hh;
            }
        }
    } else {
        // ---- A table: 32 locs per block ----
        float* Wt   = (float*)smpool;                  // [64][129]
        float* locb = (float*)(smpool + 64 * 129 * 4); // [32][64]
        #pragma unroll
        for (int it = 0; it < 32; it++) {
            int i = it * 256 + tid;
            int d = i >> 6, k = i & 63;
            Wt[k * 129 + d] = W[d * 128 + k];
        }
        size_t rbase = (size_t)(b - A0) * 32;
        #pragma unroll
        for (int it = 0; it < 8; it++) {
            int i = it * 256 + tid;
            int r = i >> 6, k = i & 63;
            locb[r * 64 + k] = loc_emb[(rbase + r) * 64 + k];
        }
        __syncthreads();
        int d  = tid & 127;
        int rh = (tid >> 7) * 16;
        #pragma unroll
        for (int rb = 0; rb < 2; rb++) {
            float acc[8] = {0, 0, 0, 0, 0, 0, 0, 0};
            #pragma unroll
            for (int k4 = 0; k4 < 16; k4++) {
                float w0 = Wt[(k4 * 4 + 0) * 129 + d];
                float w1 = Wt[(k4 * 4 + 1) * 129 + d];
                float w2 = Wt[(k4 * 4 + 2) * 129 + d];
                float w3 = Wt[(k4 * 4 + 3) * 129 + d];
                #pragma unroll
                for (int r8 = 0; r8 < 8; r8++) {
                    float4 lv = *(const float4*)&locb[(rh + rb * 8 + r8) * 64 + k4 * 4];
                    acc[r8] += w0 * lv.x + w1 * lv.y + w2 * lv.z + w3 * lv.w;
                }
            }
            #pragma unroll
            for (int r8 = 0; r8 < 8; r8++)
                d_Ah[(rbase + rh + rb * 8 + r8) * 128 + d] = __float2half_rn(acc[r8]);
        }
    }
}

// ================= launch 1: emit (tilesum+scan fused via decoupled lookback) =
__global__ __launch_bounds__(256) void k_emit() {
    __shared__ unsigned sv[TILE_H];
    __shared__ unsigned wsum[256];
    __shared__ unsigned sh_excl;
    const int tid = threadIdx.x;
    const int tb = blockIdx.x;
    size_t base = (size_t)tb * TILE_H;

    const uint4* p4 = (const uint4*)(d_cnt + base);
    #pragma unroll
    for (int it = 0; it < 8; it++) {
        size_t idx = (size_t)it * 256 + tid;
        uint4 v = (base / 4 + idx < (size_t)HMAX / 4) ? p4[idx] : make_uint4(0, 0, 0, 0);
        ((uint4*)sv)[idx] = v;
    }
    __syncthreads();

    unsigned mask = 0, mmask = 0;
    #pragma unroll
    for (int kk = 0; kk < 32; kk++) {
        int j = (kk + tid) & 31;                  // rotated: conflict-free
        unsigned v = sv[tid * 32 + j];
        if (v) mask |= 1u << j;
        if ((v >> 26) >= 2) mmask |= 1u << j;
    }
    unsigned pc = __popc(mask);
    wsum[tid] = pc;
    __syncthreads();
    for (int o = 1; o < 256; o <<= 1) {
        unsigned a = (tid >= o) ? wsum[tid - o] : 0;
        __syncthreads();
        wsum[tid] += a;
        __syncthreads();
    }
    unsigned agg = wsum[255];

    if (tid == 0) {
        if (tb == 0) { atomicExch(&d_tilestate[0], FLAG_INC | agg); sh_excl = 0; }
        else           atomicExch(&d_tilestate[tb], FLAG_AGG | agg);
    }
    __syncthreads();
    if (tb > 0 && tid < 32) {
        unsigned excl = 0;
        int j = tb - 1;
        for (;;) {
            int idx = j - tid;
            unsigned s = 0;
            if (idx >= 0) {
                do { s = *(volatile unsigned*)&d_tilestate[idx]; } while ((s >> 30) == 0);
            }
            unsigned incmask = __ballot_sync(0xffffffffu, (idx >= 0) && ((s >> 30) == 2));
            unsigned c;
            if (incmask) {
                int L0 = __ffs(incmask) - 1;
                c = ((int)tid <= L0) ? (s & VALMASK) : 0;
                #pragma unroll
                for (int o = 16; o; o >>= 1) c += __shfl_xor_sync(0xffffffffu, c, o);
                excl += c;
                break;
            }
            c = (idx >= 0) ? (s & VALMASK) : 0;
            #pragma unroll
            for (int o = 16; o; o >>= 1) c += __shfl_xor_sync(0xffffffffu, c, o);
            excl += c;
            j -= 32;
            if (j < 0) break;
        }
        if (tid == 0) {
            atomicExch(&d_tilestate[tb], FLAG_INC | ((excl + agg) & VALMASK));
            sh_excl = excl;
            if (tb == NTILES - 1) d_nuniq = excl + agg;
        }
    }
    __syncthreads();

    unsigned off = sh_excl + wsum[tid] - pc;
    while (mask) {
        int j = __ffs(mask) - 1;
        mask &= mask - 1;
        unsigned v = sv[tid * 32 + j];
        size_t idx = base + (size_t)tid * 32 + j;
        unsigned gv = v;
        if (mmask & (1u << j)) {
            // claim compact slot (order-independent: only means are formed)
            unsigned slot = atomicAdd(&d_mslots, 1u);
            gv = (v & ~CMASK) | slot;
            d_cnt[idx] = gv;                      // O(1) slot lookup for accum
            float4 z = make_float4(0.f, 0.f, 0.f, 0.f);
            float4* p = (float4*)&d_usum2[(size_t)slot * 128];
            #pragma unroll
            for (int q = 0; q < 32; q++) __stcs(&p[q], z);
        }
        d_g2[off] = make_uint2((unsigned)idx, gv);
        off++;
    }
}

__device__ __forceinline__ float2 h2f(unsigned w) { return __half22float2(*(const __half2*)&w); }

// ================= launch 2: accumulate projected user vecs into multi slots ==
__global__ __launch_bounds__(256) void k_accum(
    const int* __restrict__ x, const int* __restrict__ t, const int* __restrict__ u,
    int n)
{
    int i = blockIdx.x * blockDim.x + threadIdx.x;
    if (i >= n) return;
    unsigned h = (unsigned)t[i] * MCONST + (unsigned)x[i];
    unsigned v = d_cnt[h];
    if ((v >> 26) < 2) return;
    unsigned slot = v & CMASK;
    const uint4* cp = (const uint4*)&d_Ch[(size_t)u[i] * 128];
    float* us = &d_usum2[(size_t)slot * 128];
    #pragma unroll
    for (int q = 0; q < 16; q++) {                // 16 x uint4 = 128 halves
        uint4 cw = cp[q];
        float2 f0 = h2f(cw.x), f1 = h2f(cw.y), f2 = h2f(cw.z), f3 = h2f(cw.w);
        atomicAdd(&us[q * 8 + 0], f0.x); atomicAdd(&us[q * 8 + 1], f0.y);
        atomicAdd(&us[q * 8 + 2], f1.x); atomicAdd(&us[q * 8 + 3], f1.y);
        atomicAdd(&us[q * 8 + 4], f2.x); atomicAdd(&us[q * 8 + 5], f2.y);
        atomicAdd(&us[q * 8 + 6], f3.x); atomicAdd(&us[q * 8 + 7], f3.y);
    }
}

// ================= launch 3: output (4 rows/warp) + d_cnt cleanup ============
__device__ __forceinline__ float ftanh(float v) {
    float a = fabsf(v);
    if (a < 0.5f) {
        float s = v * v;
        return v * (1.f + s * (-0.333333333f + s * (0.133333333f + s * (-0.053968254f))));
    }
    return tanhf(v);
}

__device__ __forceinline__ void row_issue(uint2 g2, int lane,
                                          uint2& ar, uint2& br, float4& uc) {
    unsigned h = g2.x;
    unsigned c = g2.y >> 26;
    unsigned xx = h % MCONST, tt = h / MCONST;
    ar = *(const uint2*)&d_Ah[(size_t)xx * 128 + lane * 4];
    br = *(const uint2*)&d_Bh[tt * 128 + lane * 4];
    if (c == 1) {
        uint2 cr = *(const uint2*)&d_Ch[(size_t)(g2.y & CMASK) * 128 + lane * 4];
        float2 c01 = h2f(cr.x), c23 = h2f(cr.y);
        uc = make_float4(c01.x, c01.y, c23.x, c23.y);
    } else {
        float inv = 1.f / (float)c;
        float4 s4 = *(const float4*)&d_usum2[(size_t)(g2.y & CMASK) * 128 + lane * 4];
        uc = make_float4(s4.x * inv, s4.y * inv, s4.z * inv, s4.w * inv);
    }
}

__device__ __forceinline__ void row_emit(float4* o4, uint2 ar, uint2 br, float4 uc) {
    float2 a01 = h2f(ar.x), a23 = h2f(ar.y);
    float2 b01 = h2f(br.x), b23 = h2f(br.y);
    float4 r;
    r.x = ftanh(a01.x + b01.x + uc.x);
    r.y = ftanh(a01.y + b01.y + uc.y);
    r.z = ftanh(a23.x + b23.x + uc.z);
    r.w = ftanh(a23.y + b23.y + uc.w);
    __stcs(o4, r);
}

__global__ __launch_bounds__(256) void k_out(float* __restrict__ out, int n) {
    int wp   = (int)((blockIdx.x * blockDim.x + threadIdx.x) >> 5);  // warp id
    int lane = threadIdx.x & 31;
    int base = wp * 4;
    if (base >= n) return;
    unsigned nu = d_nuniq;
    const float4 zero4 = make_float4(0.f, 0.f, 0.f, 0.f);

    uint2 g[4];
    bool  inb[4], val[4];
    #pragma unroll
    for (int j = 0; j < 4; j++) {
        int r = base + j;
        inb[j] = r < n;
        g[j]   = inb[j] ? __ldcs(&d_g2[r]) : make_uint2(0u, 0u);
        val[j] = inb[j] && ((unsigned)r < nu);
    }

    uint2 ar[4], br[4];
    float4 uc[4];
    #pragma unroll
    for (int j = 0; j < 4; j++)
        if (val[j]) row_issue(g[j], lane, ar[j], br[j], uc[j]);  // all gathers in flight

    #pragma unroll
    for (int j = 0; j < 4; j++) {
        if (!inb[j]) continue;
        float4* o4 = (float4*)(out + (size_t)(base + j) * 128) + lane;
        if (val[j]) row_emit(o4, ar[j], br[j], uc[j]);
        else        __stcs(o4, zero4);
    }

    // restore the all-zero d_cnt invariant for the next graph replay:
    // lanes 0..3 each clear one of this warp's group hashes (g is warp-uniform)
    if (lane < 4 && val[lane]) d_cnt[g[lane].x] = 0u;
}

// ================= host launch =================
extern "C" void kernel_launch(void* const* d_in, const int* in_sizes, int n_in,
                              void* d_out, int out_size) {
    const float* loc_emb  = (const float*)d_in[0];
    const float* time_emb = (const float*)d_in[1];
    const float* user_emb = (const float*)d_in[2];
    const float* W        = (const float*)d_in[3];
    const float* b        = (const float*)d_in[4];
    const int*   x        = (const int*)d_in[5];
    const int*   t        = (const int*)d_in[6];
    const int*   u        = (const int*)d_in[7];
    int n    = in_sizes[5];
    int rows = out_size / 128;

    int outWarps  = (rows + 3) / 4;
    int outBlocks = (outWarps * 32 + 255) / 256;

    k_prec<<<PREGRID, 256>>>(W, loc_emb, time_emb, user_emb, b, x, t, u, n);   // 0
    k_emit<<<NTILES, 256>>>();                                                 // 1
    k_accum<<<(n + 255) / 256, 256>>>(x, t, u, n);                             // 2
    k_out<<<outBlocks, 256>>>((float*)d_out, rows);                            // 3 (ncu target)
}

// round 17
// speedup vs baseline: 1.1098x; 1.1098x over previous
#include <cuda_runtime.h>
#include <cuda_fp16.h>
#include <cstdint>
#include <cstddef>

// Problem constants (fixed by the dataset)
#define N_ROWS_MAX 1000000
#define NLOCS      100000
#define NTIMES     169
#define NUSERS1    50001
#define MCONST     100000u                  // any M > max(x) preserves (t,x) lex order
#define HMAX       (NLOCS * NTIMES)         // 16,900,000
#define TILE_H     8192                     // hashes per emit tile
#define NTILES     ((HMAX + TILE_H - 1) / TILE_H)   // 2063
#define CMASK      0x03FFFFFFu
#define VALMASK    0x3FFFFFFFu
#define FLAG_AGG   (1u << 30)
#define FLAG_INC   (2u << 30)
#define MAXSLOTS   500000                   // multi-count groups <= N/2

// ---------------- device scratch ----------------
// INVARIANT: d_cnt is all-zero at kernel_launch entry. Zero-init at module
// load covers the first call; k_out restores zeros for every touched entry
// (the group hashes in d_g2) at the end of every call.
__device__ unsigned d_cnt[HMAX];                      // (count<<26)|sum_u  (multi: |slot)
__device__ unsigned d_tilestate[NTILES];              // decoupled-lookback states
__device__ uint2    d_g2[N_ROWS_MAX];                 // (hash, packed word) per group
__device__ float    d_usum2[(size_t)MAXSLOTS * 128];  // per-slot SUM of C[u] (projected)
__device__ __half   d_Ah[(size_t)NLOCS * 128];        // fp16 W_loc @ loc_emb
__device__ __half   d_Bh[NTIMES * 128];               // fp16 W_time @ time_emb + bias
__device__ __half   d_Ch[(size_t)NUSERS1 * 128];      // fp16 W_user @ user_emb
__device__ unsigned d_nuniq;
__device__ unsigned d_mslots;                         // multi-slot allocator

// ================= launch 0: fused count + precompute tables + resets ========
#define NCNT    ((N_ROWS_MAX + 255) / 256)      // 3907
#define B0      (NCNT)
#define C0      (B0 + NTIMES)
#define NCB     ((NUSERS1 + 127) / 128)         // 391
#define A0      (C0 + NCB)
#define NAB     (NLOCS / 32)                    // 3125
#define PREGRID (A0 + NAB)

__global__ __launch_bounds__(256) void k_prec(
    const float* __restrict__ W, const float* __restrict__ loc_emb,
    const float* __restrict__ time_emb, const float* __restrict__ user_emb,
    const float* __restrict__ bias,
    const int* __restrict__ x, const int* __restrict__ t, const int* __restrict__ u,
    int n)
{
    __shared__ unsigned char smpool[41216];
    const int tid = threadIdx.x;
    const int b = blockIdx.x;

    if (b < NCNT) {
        // block 0 additionally resets lookback states + scalars (read next launch)
        if (b == 0) {
            for (int j = tid; j < NTILES; j += 256) d_tilestate[j] = 0;
            if (tid == 0) { d_nuniq = 0; d_mslots = 0; }
        }
        // ---- histogram count + packed user id ----
        int i = b * 256 + tid;
        if (i < n) {
            unsigned h = (unsigned)t[i] * MCONST + (unsigned)x[i];
            atomicAdd(&d_cnt[h], (1u << 26) | (unsigned)u[i]);
        }
    } else if (b < C0) {
        // ---- B table (one t per block), fp16 with bias folded ----
        int tt = b - B0;
        if (tid < 128) {
            int d = tid;
            float acc = bias[d];
            #pragma unroll
            for (int k = 0; k < 32; k++) acc += W[d * 128 + 64 + k] * time_emb[tt * 32 + k];
            d_Bh[tt * 128 + d] = __float2half_rn(acc);
        }
    } else if (b < A0) {
        // ---- C table: smem-tiled GEMM, 128 users per block ----
        float* Wu = (float*)smpool;                   // [32][136]
        float* Ue = (float*)(smpool + 32 * 136 * 4);  // [32][136]
        int ub = (b - C0) * 128;
        for (int i = tid; i < 128 * 32; i += 256) {
            int d = i >> 5, k = i & 31;
            Wu[k * 136 + d] = W[d * 128 + 96 + k];
        }
        for (int i = tid; i < 128 * 32; i += 256) {
            int r = i >> 5, k = i & 31;
            int uu = ub + r;
            Ue[k * 136 + r] = (uu < NUSERS1) ? user_emb[(size_t)uu * 32 + k] : 0.f;
        }
        __syncthreads();
        int tu = tid >> 4, td = tid & 15;
        float acc[8][8] = {};
        #pragma unroll
        for (int k = 0; k < 32; k++) {
            float4 u0 = *(const float4*)&Ue[k * 136 + tu * 8];
            float4 u1 = *(const float4*)&Ue[k * 136 + tu * 8 + 4];
            float4 w0 = *(const float4*)&Wu[k * 136 + td * 8];
            float4 w1 = *(const float4*)&Wu[k * 136 + td * 8 + 4];
            float uv[8] = {u0.x, u0.y, u0.z, u0.w, u1.x, u1.y, u1.z, u1.w};
            float wv[8] = {w0.x, w0.y, w0.z, w0.w, w1.x, w1.y, w1.z, w1.w};
            #pragma unroll
            for (int j = 0; j < 8; j++)
                #pragma unroll
                for (int m = 0; m < 8; m++) acc[j][m] += uv[j] * wv[m];
        }
        #pragma unroll
        for (int j = 0; j < 8; j++) {
            int uu = ub + tu * 8 + j;
            if (uu < NUSERS1) {
                __half hh[8];
                #pragma unroll
                for (int m = 0; m < 8; m++) hh[m] = __float2half_rn(acc[j][m]);
                *(uint4*)&d_Ch[(size_t)uu * 128 + td * 8] = *(const uint4*)hh;
            }
        }
    } else {
        // ---- A table: 32 locs per block ----
        float* Wt   = (float*)smpool;                  // [64][129]
        float* locb = (float*)(smpool + 64 * 129 * 4); // [32][64]
        #pragma unroll
        for (int it = 0; it < 32; it++) {
            int i = it * 256 + tid;
            int d = i >> 6, k = i & 63;
            Wt[k * 129 + d] = W[d * 128 + k];
        }
        size_t rbase = (size_t)(b - A0) * 32;
        #pragma unroll
        for (int it = 0; it < 8; it++) {
            int i = it * 256 + tid;
            int r = i >> 6, k = i & 63;
            locb[r * 64 + k] = loc_emb[(rbase + r) * 64 + k];
        }
        __syncthreads();
        int d  = tid & 127;
        int rh = (tid >> 7) * 16;
        #pragma unroll
        for (int rb = 0; rb < 2; rb++) {
            float acc[8] = {0, 0, 0, 0, 0, 0, 0, 0};
            #pragma unroll
            for (int k4 = 0; k4 < 16; k4++) {
                float w0 = Wt[(k4 * 4 + 0) * 129 + d];
                float w1 = Wt[(k4 * 4 + 1) * 129 + d];
                float w2 = Wt[(k4 * 4 + 2) * 129 + d];
                float w3 = Wt[(k4 * 4 + 3) * 129 + d];
                #pragma unroll
                for (int r8 = 0; r8 < 8; r8++) {
                    float4 lv = *(const float4*)&locb[(rh + rb * 8 + r8) * 64 + k4 * 4];
                    acc[r8] += w0 * lv.x + w1 * lv.y + w2 * lv.z + w3 * lv.w;
                }
            }
            #pragma unroll
            for (int r8 = 0; r8 < 8; r8++)
                d_Ah[(rbase + rh + rb * 8 + r8) * 128 + d] = __float2half_rn(acc[r8]);
        }
    }
}

// ================= launch 1: emit (tilesum+scan fused via decoupled lookback) =
__global__ __launch_bounds__(256) void k_emit() {
    __shared__ unsigned sv[TILE_H];
    __shared__ unsigned wsum[256];
    __shared__ unsigned sh_excl;
    const int tid = threadIdx.x;
    const int tb = blockIdx.x;
    size_t base = (size_t)tb * TILE_H;

    const uint4* p4 = (const uint4*)(d_cnt + base);
    #pragma unroll
    for (int it = 0; it < 8; it++) {
        size_t idx = (size_t)it * 256 + tid;
        uint4 v = (base / 4 + idx < (size_t)HMAX / 4) ? p4[idx] : make_uint4(0, 0, 0, 0);
        ((uint4*)sv)[idx] = v;
    }
    __syncthreads();

    unsigned mask = 0, mmask = 0;
    #pragma unroll
    for (int kk = 0; kk < 32; kk++) {
        int j = (kk + tid) & 31;                  // rotated: conflict-free
        unsigned v = sv[tid * 32 + j];
        if (v) mask |= 1u << j;
        if ((v >> 26) >= 2) mmask |= 1u << j;
    }
    unsigned pc = __popc(mask);
    wsum[tid] = pc;
    __syncthreads();
    for (int o = 1; o < 256; o <<= 1) {
        unsigned a = (tid >= o) ? wsum[tid - o] : 0;
        __syncthreads();
        wsum[tid] += a;
        __syncthreads();
    }
    unsigned agg = wsum[255];

    if (tid == 0) {
        if (tb == 0) { atomicExch(&d_tilestate[0], FLAG_INC | agg); sh_excl = 0; }
        else           atomicExch(&d_tilestate[tb], FLAG_AGG | agg);
    }
    __syncthreads();
    if (tb > 0 && tid < 32) {
        unsigned excl = 0;
        int j = tb - 1;
        for (;;) {
            int idx = j - tid;
            unsigned s = 0;
            if (idx >= 0) {
                do { s = *(volatile unsigned*)&d_tilestate[idx]; } while ((s >> 30) == 0);
            }
            unsigned incmask = __ballot_sync(0xffffffffu, (idx >= 0) && ((s >> 30) == 2));
            unsigned c;
            if (incmask) {
                int L0 = __ffs(incmask) - 1;
                c = ((int)tid <= L0) ? (s & VALMASK) : 0;
                #pragma unroll
                for (int o = 16; o; o >>= 1) c += __shfl_xor_sync(0xffffffffu, c, o);
                excl += c;
                break;
            }
            c = (idx >= 0) ? (s & VALMASK) : 0;
            #pragma unroll
            for (int o = 16; o; o >>= 1) c += __shfl_xor_sync(0xffffffffu, c, o);
            excl += c;
            j -= 32;
            if (j < 0) break;
        }
        if (tid == 0) {
            atomicExch(&d_tilestate[tb], FLAG_INC | ((excl + agg) & VALMASK));
            sh_excl = excl;
            if (tb == NTILES - 1) d_nuniq = excl + agg;
        }
    }
    __syncthreads();

    unsigned off = sh_excl + wsum[tid] - pc;
    while (mask) {
        int j = __ffs(mask) - 1;
        mask &= mask - 1;
        unsigned v = sv[tid * 32 + j];
        size_t idx = base + (size_t)tid * 32 + j;
        unsigned gv = v;
        if (mmask & (1u << j)) {
            // claim compact slot (order-independent: only means are formed)
            unsigned slot = atomicAdd(&d_mslots, 1u);
            gv = (v & ~CMASK) | slot;
            d_cnt[idx] = gv;                      // O(1) slot lookup for accum
            float4 z = make_float4(0.f, 0.f, 0.f, 0.f);
            float4* p = (float4*)&d_usum2[(size_t)slot * 128];
            #pragma unroll
            for (int q = 0; q < 32; q++) __stcs(&p[q], z);
        }
        d_g2[off] = make_uint2((unsigned)idx, gv);
        off++;
    }
}

__device__ __forceinline__ float2 h2f(unsigned w) { return __half22float2(*(const __half2*)&w); }

// ================= launch 2: accumulate projected user vecs into multi slots ==
__global__ __launch_bounds__(256) void k_accum(
    const int* __restrict__ x, const int* __restrict__ t, const int* __restrict__ u,
    int n)
{
    int i = blockIdx.x * blockDim.x + threadIdx.x;
    if (i >= n) return;
    unsigned h = (unsigned)t[i] * MCONST + (unsigned)x[i];
    unsigned v = d_cnt[h];
    if ((v >> 26) < 2) return;
    unsigned slot = v & CMASK;
    const uint4* cp = (const uint4*)&d_Ch[(size_t)u[i] * 128];
    float* us = &d_usum2[(size_t)slot * 128];
    #pragma unroll
    for (int q = 0; q < 16; q++) {                // 16 x uint4 = 128 halves
        uint4 cw = cp[q];
        float2 f0 = h2f(cw.x), f1 = h2f(cw.y), f2 = h2f(cw.z), f3 = h2f(cw.w);
        atomicAdd(&us[q * 8 + 0], f0.x); atomicAdd(&us[q * 8 + 1], f0.y);
        atomicAdd(&us[q * 8 + 2], f1.x); atomicAdd(&us[q * 8 + 3], f1.y);
        atomicAdd(&us[q * 8 + 4], f2.x); atomicAdd(&us[q * 8 + 5], f2.y);
        atomicAdd(&us[q * 8 + 6], f3.x); atomicAdd(&us[q * 8 + 7], f3.y);
    }
}

// ================= launch 3: output (2 rows/warp) + d_cnt cleanup ============
__device__ __forceinline__ float ftanh(float v) {
    float a = fabsf(v);
    if (a < 0.5f) {
        float s = v * v;
        return v * (1.f + s * (-0.333333333f + s * (0.133333333f + s * (-0.053968254f))));
    }
    return tanhf(v);
}

__device__ __forceinline__ void row_issue(uint2 g2, int lane,
                                          uint2& ar, uint2& br, float4& uc) {
    unsigned h = g2.x;
    unsigned c = g2.y >> 26;
    unsigned xx = h % MCONST, tt = h / MCONST;
    ar = *(const uint2*)&d_Ah[(size_t)xx * 128 + lane * 4];
    br = *(const uint2*)&d_Bh[tt * 128 + lane * 4];
    if (c == 1) {
        uint2 cr = *(const uint2*)&d_Ch[(size_t)(g2.y & CMASK) * 128 + lane * 4];
        float2 c01 = h2f(cr.x), c23 = h2f(cr.y);
        uc = make_float4(c01.x, c01.y, c23.x, c23.y);
    } else {
        float inv = 1.f / (float)c;
        float4 s4 = *(const float4*)&d_usum2[(size_t)(g2.y & CMASK) * 128 + lane * 4];
        uc = make_float4(s4.x * inv, s4.y * inv, s4.z * inv, s4.w * inv);
    }
}

__device__ __forceinline__ void row_emit(float4* o4, uint2 ar, uint2 br, float4 uc) {
    float2 a01 = h2f(ar.x), a23 = h2f(ar.y);
    float2 b01 = h2f(br.x), b23 = h2f(br.y);
    float4 r;
    r.x = ftanh(a01.x + b01.x + uc.x);
    r.y = ftanh(a01.y + b01.y + uc.y);
    r.z = ftanh(a23.x + b23.x + uc.z);
    r.w = ftanh(a23.y + b23.y + uc.w);
    __stcs(o4, r);
}

__global__ __launch_bounds__(256) void k_out(float* __restrict__ out, int n) {
    int wp   = (int)((blockIdx.x * blockDim.x + threadIdx.x) >> 5);  // warp id
    int lane = threadIdx.x & 31;
    int r0 = wp * 2, r1 = r0 + 1;
    if (r0 >= n) return;
    unsigned nu = d_nuniq;
    const float4 zero4 = make_float4(0.f, 0.f, 0.f, 0.f);

    uint2 g0 = __ldcs(&d_g2[r0]);                    // one-touch stream
    uint2 g1 = (r1 < n) ? __ldcs(&d_g2[r1]) : make_uint2(0u, 0u);
    bool v0 = (unsigned)r0 < nu;
    bool v1 = (r1 < n) && ((unsigned)r1 < nu);

    uint2 ar0, br0, ar1, br1;
    float4 uc0, uc1;
    if (v0) row_issue(g0, lane, ar0, br0, uc0);      // both rows' gathers in flight
    if (v1) row_issue(g1, lane, ar1, br1, uc1);

    float4* o0 = (float4*)(out + (size_t)r0 * 128) + lane;
    if (v0) row_emit(o0, ar0, br0, uc0); else __stcs(o0, zero4);
    if (r1 < n) {
        float4* o1 = (float4*)(out + (size_t)r1 * 128) + lane;
        if (v1) row_emit(o1, ar1, br1, uc1); else __stcs(o1, zero4);
    }

    // restore the all-zero d_cnt invariant for the next graph replay:
    // lanes 0..1 each clear one of this warp's group hashes (g is warp-uniform)
    if (lane == 0 && v0) d_cnt[g0.x] = 0u;
    if (lane == 1 && v1) d_cnt[g1.x] = 0u;
}

// ================= host launch =================
extern "C" void kernel_launch(void* const* d_in, const int* in_sizes, int n_in,
                              void* d_out, int out_size) {
    const float* loc_emb  = (const float*)d_in[0];
    const float* time_emb = (const float*)d_in[1];
    const float* user_emb = (const float*)d_in[2];
    const float* W        = (const float*)d_in[3];
    const float* b        = (const float*)d_in[4];
    const int*   x        = (const int*)d_in[5];
    const int*   t        = (const int*)d_in[6];
    const int*   u        = (const int*)d_in[7];
    int n    = in_sizes[5];
    int rows = out_size / 128;

    int outWarps  = (rows + 1) / 2;
    int outBlocks = (outWarps * 32 + 255) / 256;

    k_prec<<<PREGRID, 256>>>(W, loc_emb, time_emb, user_emb, b, x, t, u, n);   // 0
    k_emit<<<NTILES, 256>>>();                                                 // 1
    k_accum<<<(n + 255) / 256, 256>>>(x, t, u, n);                             // 2
    k_out<<<outBlocks, 256>>>((float*)d_out, rows);                            // 3 (ncu target)
}